// round 1
// baseline (speedup 1.0000x reference)
#include <cuda_runtime.h>
#include <cuda_bf16.h>
#include <math.h>

#define BB 16
#define LSEQ 1536
#define DIM 512
#define DFF 2048
#define MROWS (BB*LSEQ)   // 24576
#define TOPK 7

// ------------------------- scratch (__device__ globals) -------------------------
__device__ float g_Q [MROWS*DIM];
__device__ float g_K [MROWS*DIM];
__device__ float g_V [MROWS*DIM];
__device__ float g_O [MROWS*DIM];
__device__ float g_T1[MROWS*DIM];
__device__ float g_T2[MROWS*DIM];
__device__ float g_T3[MROWS*DIM];
__device__ float g_T4[MROWS*DIM];
__device__ float g_G [ (long long)BB*LSEQ*LSEQ ];   // 151 MB
__device__ float g_FF[ (long long)MROWS*DFF ];      // 201 MB
__device__ float g_IC[ (long long)MROWS*3*DIM ];    // 151 MB
__device__ float g_WT[ DIM*3*DIM ];
__device__ float g_MV[ BB*LSEQ ];
__device__ float g_WTS[ BB*8 ];
__device__ int   g_IDX[ 8 ];

// ------------------------- SGEMM: C = A @ Bw^T (+bias)(+resid)(relu) -------------------------
// A [M,K] row-major, Bw [N,K] row-major. Batched via blockIdx.z with strides.
// flags: 1 = relu, 2 = add resid (resid same layout as C, batch=1 only)
#define TM 128
#define TN 128
#define TKK 8

__global__ void sgemm_kernel(const float* __restrict__ A, const float* __restrict__ Bw,
                             const float* __restrict__ bias, const float* __restrict__ resid,
                             float* __restrict__ C,
                             int M, int N, int K,
                             long long sA, long long sB, long long sC, int flags)
{
    long long bz = blockIdx.z;
    A  += bz * sA;
    Bw += bz * sB;
    C  += bz * sC;

    __shared__ float As[TKK][TM];
    __shared__ float Bs[TKK][TN];

    int tid  = threadIdx.x;          // 256 threads
    int m0   = blockIdx.y * TM;
    int n0   = blockIdx.x * TN;
    int arow = tid >> 1;             // 0..127
    int acol = (tid & 1) * 4;        // 0 or 4
    int tx   = tid & 15;
    int ty   = tid >> 4;

    float acc[8][8];
    #pragma unroll
    for (int i = 0; i < 8; i++)
        #pragma unroll
        for (int j = 0; j < 8; j++) acc[i][j] = 0.f;

    for (int k0 = 0; k0 < K; k0 += TKK) {
        float4 av = *(const float4*)(A  + (long long)(m0 + arow) * K + k0 + acol);
        float4 bv = *(const float4*)(Bw + (long long)(n0 + arow) * K + k0 + acol);
        As[acol+0][arow] = av.x; As[acol+1][arow] = av.y;
        As[acol+2][arow] = av.z; As[acol+3][arow] = av.w;
        Bs[acol+0][arow] = bv.x; Bs[acol+1][arow] = bv.y;
        Bs[acol+2][arow] = bv.z; Bs[acol+3][arow] = bv.w;
        __syncthreads();

        #pragma unroll
        for (int kk = 0; kk < TKK; kk++) {
            float4 a0 = *(const float4*)&As[kk][ty*8];
            float4 a1 = *(const float4*)&As[kk][ty*8 + 4];
            float4 b0 = *(const float4*)&Bs[kk][tx*8];
            float4 b1 = *(const float4*)&Bs[kk][tx*8 + 4];
            float a[8] = {a0.x,a0.y,a0.z,a0.w,a1.x,a1.y,a1.z,a1.w};
            float b[8] = {b0.x,b0.y,b0.z,b0.w,b1.x,b1.y,b1.z,b1.w};
            #pragma unroll
            for (int i = 0; i < 8; i++)
                #pragma unroll
                for (int j = 0; j < 8; j++)
                    acc[i][j] += a[i] * b[j];
        }
        __syncthreads();
    }

    #pragma unroll
    for (int i = 0; i < 8; i++) {
        int m = m0 + ty*8 + i;
        #pragma unroll
        for (int j = 0; j < 8; j++) {
            int n = n0 + tx*8 + j;
            float v = acc[i][j];
            if (bias) v += bias[n];
            if (flags & 2) v += resid[(long long)m * N + n];
            if (flags & 1) v = fmaxf(v, 0.f);
            C[(long long)m * N + n] = v;
        }
    }
}

// ------------------------- wrapped-diagonal sum of Gram matrix -------------------------
// MV[b,tau] += sum_t G[b, t, (t - tau) mod L]   (each element G[t,u] -> tau = (t-u) mod L)
__global__ void diagsum_kernel(const float* __restrict__ G, float* __restrict__ MV)
{
    __shared__ float bins[LSEQ];
    int tid = threadIdx.x;   // 256
    for (int i = tid; i < LSEQ; i += 256) bins[i] = 0.f;
    __syncthreads();

    int b  = blockIdx.y;
    int t0 = blockIdx.x * 64;
    const float* Gb = G + (long long)b * LSEQ * LSEQ;
    for (int t = t0; t < t0 + 64; t++) {
        const float* row = Gb + (long long)t * LSEQ;
        for (int u = tid; u < LSEQ; u += 256) {
            int tau = t - u; if (tau < 0) tau += LSEQ;
            atomicAdd(&bins[tau], row[u]);
        }
    }
    __syncthreads();
    for (int i = tid; i < LSEQ; i += 256) atomicAdd(&MV[b*LSEQ + i], bins[i]);
}

// ------------------------- top-7 delays + per-batch softmax weights -------------------------
__global__ void topk_kernel(const float* __restrict__ MV, int* __restrict__ idx_out,
                            float* __restrict__ w_out)
{
    __shared__ float g[LSEQ];
    __shared__ float rv[256];
    __shared__ int   ri[256];
    __shared__ int   s_idx[TOPK];
    int tid = threadIdx.x;   // 256

    for (int t = tid; t < LSEQ; t += 256) {
        float s = 0.f;
        for (int b = 0; b < BB; b++) s += MV[b*LSEQ + t];
        g[t] = s;
    }
    __syncthreads();

    for (int it = 0; it < TOPK; it++) {
        float best = -INFINITY; int bi = 0;
        for (int t = tid; t < LSEQ; t += 256)
            if (g[t] > best) { best = g[t]; bi = t; }
        rv[tid] = best; ri[tid] = bi;
        __syncthreads();
        for (int s = 128; s > 0; s >>= 1) {
            if (tid < s && rv[tid + s] > rv[tid]) { rv[tid] = rv[tid+s]; ri[tid] = ri[tid+s]; }
            __syncthreads();
        }
        if (tid == 0) { s_idx[it] = ri[0]; g[ri[0]] = -INFINITY; idx_out[it] = ri[0]; }
        __syncthreads();
    }

    if (tid < BB) {
        int b = tid;
        float wv[TOPK]; float m = -INFINITY;
        for (int i = 0; i < TOPK; i++) {
            wv[i] = MV[b*LSEQ + s_idx[i]] * (1.0f / (float)DIM);
            m = fmaxf(m, wv[i]);
        }
        float s = 0.f;
        for (int i = 0; i < TOPK; i++) { wv[i] = expf(wv[i] - m); s += wv[i]; }
        for (int i = 0; i < TOPK; i++) w_out[b*TOPK + i] = wv[i] / s;
    }
}

// ------------------------- time-delay aggregation -------------------------
// O[b,t,d] = sum_i w[b,i] * V[b, (t+idx_i)%L, d]
__global__ void aggregate_kernel(const float* __restrict__ V, const int* __restrict__ idx,
                                 const float* __restrict__ w, float* __restrict__ O)
{
    int bt = blockIdx.x;
    int b  = bt / LSEQ, t = bt % LSEQ;
    __shared__ int   s_i[TOPK];
    __shared__ float s_w[TOPK];
    if (threadIdx.x < TOPK) { s_i[threadIdx.x] = idx[threadIdx.x]; s_w[threadIdx.x] = w[b*TOPK + threadIdx.x]; }
    __syncthreads();
    int d4 = threadIdx.x;   // 128 threads, float4 over D=512
    float4 acc = {0.f,0.f,0.f,0.f};
    #pragma unroll
    for (int i = 0; i < TOPK; i++) {
        int tt = t + s_i[i]; if (tt >= LSEQ) tt -= LSEQ;
        float4 v = *(const float4*)&V[((long long)(b*LSEQ + tt))*DIM + d4*4];
        acc.x += s_w[i]*v.x; acc.y += s_w[i]*v.y; acc.z += s_w[i]*v.z; acc.w += s_w[i]*v.w;
    }
    *(float4*)&O[((long long)bt)*DIM + d4*4] = acc;
}

// ------------------------- series_decomp: dst = src - movavg_25(src) -------------------------
__global__ void decomp_kernel(const float* __restrict__ src, float* __restrict__ dst)
{
    int d  = blockIdx.x * blockDim.x + threadIdx.x;  // 0..511
    int b  = blockIdx.y;
    int t0 = blockIdx.z * 128;
    const float* s = src + (long long)b * LSEQ * DIM + d;
    float*       o = dst + (long long)b * LSEQ * DIM + d;

    float sum = 0.f;
    for (int j = t0 - 12; j <= t0 + 12; j++) {
        int jc = j; if (jc < 0) jc = 0; if (jc > LSEQ-1) jc = LSEQ-1;
        sum += s[(long long)jc * DIM];
    }
    for (int t = t0; t < t0 + 128; t++) {
        o[(long long)t * DIM] = s[(long long)t * DIM] - sum * (1.0f/25.0f);
        int ja = t + 13; if (ja > LSEQ-1) ja = LSEQ-1;
        int jr = t - 12; if (jr < 0) jr = 0;
        sum += s[(long long)ja * DIM] - s[(long long)jr * DIM];
    }
}

// ------------------------- im2col for circular conv1d k=3 -------------------------
__global__ void im2col_kernel(const float* __restrict__ x, float* __restrict__ ic)
{
    long long i = (long long)blockIdx.x * blockDim.x + threadIdx.x;
    const long long total = (long long)BB * LSEQ * 3 * (DIM/4);
    if (i >= total) return;
    int c4 = (int)(i % (DIM/4));
    long long r = i / (DIM/4);
    int j = (int)(r % 3);
    long long bt = r / 3;
    int t = (int)(bt % LSEQ);
    int b = (int)(bt / LSEQ);
    int ts = t + j - 1; if (ts < 0) ts += LSEQ; if (ts >= LSEQ) ts -= LSEQ;
    float4 v = *(const float4*)&x[((long long)(b*LSEQ + ts))*DIM + c4*4];
    *(float4*)&ic[(bt*3 + j)*DIM + (long long)c4*4] = v;
}

// ------------------------- repack conv weight (O,I,3) -> [O, 3*I] matching im2col -------------------------
__global__ void repack_kernel(const float* __restrict__ W, float* __restrict__ out)
{
    int i = blockIdx.x * blockDim.x + threadIdx.x;
    const int total = DIM * 3 * DIM;
    if (i >= total) return;
    int o = i / (3*DIM);
    int k = i % (3*DIM);
    int j = k / DIM, c = k % DIM;
    out[i] = W[((long long)o*DIM + c)*3 + j];
}

// ------------------------- host orchestration -------------------------
static void launch_gemm(const float* A, const float* Bw, const float* bias, const float* resid,
                        float* C, int M, int N, int K, int batch,
                        long long sA, long long sB, long long sC, int flags)
{
    dim3 grid(N/TN, M/TM, batch);
    sgemm_kernel<<<grid, 256>>>(A, Bw, bias, resid, C, M, N, K, sA, sB, sC, flags);
}

extern "C" void kernel_launch(void* const* d_in, const int* in_sizes, int n_in,
                              void* d_out, int out_size)
{
    const float* x_s      = (const float*)d_in[0];
    const float* x_w      = (const float*)d_in[1];
    const float* wc1_W    = (const float*)d_in[2];
    const float* wc1_b    = (const float*)d_in[3];
    const float* wc2_W    = (const float*)d_in[4];
    const float* wc2_b    = (const float*)d_in[5];
    const float* attn_W   = (const float*)d_in[6];
    const float* attn_b   = (const float*)d_in[7];
    const float* wc1_proj = (const float*)d_in[8];
    const float* wc2_proj = (const float*)d_in[9];
    const float* conv1_W  = (const float*)d_in[10];
    const float* conv2_W  = (const float*)d_in[11];

    float* out_res = (float*)d_out;
    float* out_xw  = out_res + (long long)MROWS * DIM;

    float *pQ,*pK,*pV,*pO,*pT1,*pT2,*pT3,*pT4,*pG,*pFF,*pIC,*pWT,*pMV,*pWTS;
    int* pIDX;
    cudaGetSymbolAddress((void**)&pQ,  g_Q);
    cudaGetSymbolAddress((void**)&pK,  g_K);
    cudaGetSymbolAddress((void**)&pV,  g_V);
    cudaGetSymbolAddress((void**)&pO,  g_O);
    cudaGetSymbolAddress((void**)&pT1, g_T1);
    cudaGetSymbolAddress((void**)&pT2, g_T2);
    cudaGetSymbolAddress((void**)&pT3, g_T3);
    cudaGetSymbolAddress((void**)&pT4, g_T4);
    cudaGetSymbolAddress((void**)&pG,  g_G);
    cudaGetSymbolAddress((void**)&pFF, g_FF);
    cudaGetSymbolAddress((void**)&pIC, g_IC);
    cudaGetSymbolAddress((void**)&pWT, g_WT);
    cudaGetSymbolAddress((void**)&pMV, g_MV);
    cudaGetSymbolAddress((void**)&pWTS,g_WTS);
    cudaGetSymbolAddress((void**)&pIDX,g_IDX);

    const long long DD2 = (long long)DIM * DIM;

    // attn_layer helper (lambda): q from qin, k=v from kin; dest = resid + attn_out
    auto run_attn = [&](const float* qin, const float* kin, const float* W, const float* bvec,
                        const float* resid, float* dest)
    {
        launch_gemm(qin, W + 0*DD2, bvec + 0*DIM, nullptr, pQ, MROWS, DIM, DIM, 1, 0,0,0, 0);
        launch_gemm(kin, W + 1*DD2, bvec + 1*DIM, nullptr, pK, MROWS, DIM, DIM, 1, 0,0,0, 0);
        launch_gemm(kin, W + 2*DD2, bvec + 2*DIM, nullptr, pV, MROWS, DIM, DIM, 1, 0,0,0, 0);
        cudaMemsetAsync(pMV, 0, BB*LSEQ*sizeof(float));
        // per-batch Gram: G[b] = Q[b] @ K[b]^T
        launch_gemm(pQ, pK, nullptr, nullptr, pG, LSEQ, LSEQ, DIM, BB,
                    (long long)LSEQ*DIM, (long long)LSEQ*DIM, (long long)LSEQ*LSEQ, 0);
        diagsum_kernel<<<dim3(LSEQ/64, BB), 256>>>(pG, pMV);
        topk_kernel<<<1, 256>>>(pMV, pIDX, pWTS);
        aggregate_kernel<<<MROWS, 128>>>(pV, pIDX, pWTS, pO);
        launch_gemm(pO, W + 3*DD2, bvec + 3*DIM, resid, dest, MROWS, DIM, DIM, 1, 0,0,0, 2);
    };

    auto run_embed = [&](const float* x, const float* Wproj, float* dest)
    {
        repack_kernel<<<(DIM*3*DIM + 255)/256, 256>>>(Wproj, pWT);
        im2col_kernel<<<(unsigned)(((long long)BB*LSEQ*3*(DIM/4) + 255)/256), 256>>>(x, pIC);
        launch_gemm(pIC, pWT, nullptr, nullptr, dest, MROWS, DIM, 3*DIM, 1, 0,0,0, 0);
    };

    // 1) x_s1 = x_s + attn(q=x_w, k=v=x_s ; wc1)          -> T1
    run_attn(x_w, x_s, wc1_W, wc1_b, x_s, pT1);
    // 2) x_w1 = token_embed(x_w, wc1_proj)                 -> T2
    run_embed(x_w, wc1_proj, pT2);
    // 3) x_s2 = x_s1 + attn(x_s1 ; attn_W)                 -> T3
    run_attn(pT1, pT1, attn_W, attn_b, pT1, pT3);
    // 4) x_s3 = decomp(x_s2)                               -> T4
    decomp_kernel<<<dim3(DIM/128, BB, LSEQ/128), 128>>>(pT3, pT4);
    // 5) x_s4 = x_s3 + attn(q=x_w1, k=v=x_s3 ; wc2)        -> T1
    run_attn(pT2, pT4, wc2_W, wc2_b, pT4, pT1);
    // 6) x_w_new = token_embed(x_w1, wc2_proj)             -> out_xw
    run_embed(pT2, wc2_proj, out_xw);
    // 7) FFN: y = relu(x_s4 @ conv1^T) @ conv2^T ; tmp = x_s4 + y  -> T3
    launch_gemm(pT1, conv1_W, nullptr, nullptr, pFF, MROWS, DFF, DIM, 1, 0,0,0, 1);
    launch_gemm(pFF, conv2_W, nullptr, pT1, pT3, MROWS, DIM, DFF, 1, 0,0,0, 2);
    // 8) res = decomp(tmp)                                 -> out_res
    decomp_kernel<<<dim3(DIM/128, BB, LSEQ/128), 128>>>(pT3, out_res);
}

// round 3
// speedup vs baseline: 3.5946x; 3.5946x over previous
#include <cuda_runtime.h>
#include <cuda_bf16.h>
#include <math.h>
#include <stdint.h>

#define BB 16
#define LSEQ 1536
#define DIM 512
#define DFF 2048
#define MROWS (BB*LSEQ)   // 24576
#define TOPK 7

// ------------------------- scratch (__device__ globals) -------------------------
__device__ float g_Q [MROWS*DIM];
__device__ float g_K [MROWS*DIM];
__device__ float g_V [MROWS*DIM];
__device__ float g_O [MROWS*DIM];
__device__ float g_T1[MROWS*DIM];
__device__ float g_T2[MROWS*DIM];
__device__ float g_T3[MROWS*DIM];
__device__ float g_T4[MROWS*DIM];
__device__ float g_FF[ (long long)MROWS*DFF ];      // 201 MB
__device__ float g_IC[ (long long)MROWS*3*DIM ];    // 151 MB
__device__ float g_WT[ DIM*3*DIM ];
__device__ float g_MV[ BB*LSEQ ];
__device__ float g_WTS[ BB*8 ];
__device__ int   g_IDX[ 8 ];

// ======================= HMMA GEMM (split bf16, fp32 accuracy) =======================
// C[M,N] = A[M,K] @ Bw[N,K]^T (+bias)(+resid)(relu), or Gram diag-sum mode.
// flags: 1=relu, 2=add resid, 4=gram (reduce wrapped diagonals into MV[bz*L+tau])
//
// CTA tile 128x128, K chunk 32 (fp32). smem per stage: Ahi|Alo|Bhi|Blo, each
// 128 rows x 32 bf16, row stride 80 B (64 data + 16 pad -> ldmatrix conflict-free).
#define RS 80
#define COMP 10240          // 128*80
#define STAGE (4*COMP)      // 40960
#define DYN_SMEM (2*STAGE)  // 81920

__device__ __forceinline__ uint32_t smem_u32(const void* p) {
    uint32_t a;
    asm("{ .reg .u64 t; cvta.to.shared.u64 t, %1; cvt.u32.u64 %0, t; }" : "=r"(a) : "l"(p));
    return a;
}
__device__ __forceinline__ void ldsm_x4(uint32_t* r, uint32_t addr) {
    asm volatile("ldmatrix.sync.aligned.m8n8.x4.shared.b16 {%0,%1,%2,%3}, [%4];"
                 : "=r"(r[0]), "=r"(r[1]), "=r"(r[2]), "=r"(r[3]) : "r"(addr));
}
__device__ __forceinline__ void mma16816(float* d, const uint32_t* a, const uint32_t* b) {
    asm volatile("mma.sync.aligned.m16n8k16.row.col.f32.bf16.bf16.f32 "
                 "{%0,%1,%2,%3}, {%4,%5,%6,%7}, {%8,%9}, {%0,%1,%2,%3};"
                 : "+f"(d[0]), "+f"(d[1]), "+f"(d[2]), "+f"(d[3])
                 : "r"(a[0]), "r"(a[1]), "r"(a[2]), "r"(a[3]), "r"(b[0]), "r"(b[1]));
}

__device__ __forceinline__ void ldg_chunk(const float* __restrict__ A, const float* __restrict__ B,
                                          int K, int m0, int n0, int k0, int tid,
                                          float4* va, float4* vb)
{
    #pragma unroll
    for (int i = 0; i < 4; i++) {
        int idx = i*256 + tid;
        int row = idx >> 3, c4 = idx & 7;
        va[i] = *(const float4*)(A + (long long)(m0+row)*K + k0 + c4*4);
        vb[i] = *(const float4*)(B + (long long)(n0+row)*K + k0 + c4*4);
    }
}

__device__ __forceinline__ void split_store(char* dsthi, const float4* v, int tid)
{
    #pragma unroll
    for (int i = 0; i < 4; i++) {
        int idx = i*256 + tid;
        int row = idx >> 3, c4 = idx & 7;
        __nv_bfloat162 h0 = __floats2bfloat162_rn(v[i].x, v[i].y);
        __nv_bfloat162 h1 = __floats2bfloat162_rn(v[i].z, v[i].w);
        uint32_t h0u = *(const uint32_t*)&h0, h1u = *(const uint32_t*)&h1;
        float l0x = v[i].x - __uint_as_float(h0u << 16);
        float l0y = v[i].y - __uint_as_float(h0u & 0xffff0000u);
        float l1x = v[i].z - __uint_as_float(h1u << 16);
        float l1y = v[i].w - __uint_as_float(h1u & 0xffff0000u);
        __nv_bfloat162 g0 = __floats2bfloat162_rn(l0x, l0y);
        __nv_bfloat162 g1 = __floats2bfloat162_rn(l1x, l1y);
        int off = row*RS + c4*8;
        *(uint2*)(dsthi + off)        = make_uint2(h0u, h1u);
        *(uint2*)(dsthi + COMP + off) = make_uint2(*(const uint32_t*)&g0, *(const uint32_t*)&g1);
    }
}

__global__ void __launch_bounds__(256, 1) gemm_tc_kernel(
    const float* __restrict__ A, const float* __restrict__ Bw,
    const float* __restrict__ bias, const float* __restrict__ resid,
    float* __restrict__ C, float* __restrict__ MV,
    int M, int N, int K,
    long long sA, long long sB, long long sC, int flags)
{
    extern __shared__ char smem[];
    uint32_t sb = smem_u32(smem);
    int tid = threadIdx.x;
    int lane = tid & 31, w = tid >> 5;
    int wm = w >> 2, wn = w & 3;          // warp tile: rows wm*64..+63, cols wn*32..+31
    long long bz = blockIdx.z;
    const float* Ab = A + bz * sA;
    const float* Bb = Bw + bz * sB;
    int n0 = blockIdx.x * 128, m0 = blockIdx.y * 128;

    // ldmatrix lane bases
    int aRow = wm*64 + (lane & 15);
    int bRow = wn*32 + (lane & 15);
    int colHalf = (lane >> 4) * 16;
    uint32_t aOff = (uint32_t)(aRow*RS + colHalf);
    uint32_t bOff = (uint32_t)(2*COMP + bRow*RS + colHalf);

    float acc[4][4][4];
    #pragma unroll
    for (int i = 0; i < 4; i++)
        #pragma unroll
        for (int j = 0; j < 4; j++)
            #pragma unroll
            for (int r = 0; r < 4; r++) acc[i][j][r] = 0.f;

    const int nch = K / 32;
    float4 va[4], vb[4];

    ldg_chunk(Ab, Bb, K, m0, n0, 0, tid, va, vb);
    split_store(smem, va, tid);
    split_store(smem + 2*COMP, vb, tid);
    __syncthreads();

    for (int ch = 0; ch < nch; ch++) {
        if (ch + 1 < nch) ldg_chunk(Ab, Bb, K, m0, n0, (ch+1)*32, tid, va, vb);

        uint32_t st = sb + (uint32_t)((ch & 1) * STAGE);
        #pragma unroll
        for (int ks = 0; ks < 2; ks++) {
            uint32_t ah[4][4], al[4][4], bh[4][2], bl[4][2];
            #pragma unroll
            for (int mt = 0; mt < 4; mt++) {
                ldsm_x4(ah[mt], st + aOff + mt*(16*RS) + ks*32);
                ldsm_x4(al[mt], st + COMP + aOff + mt*(16*RS) + ks*32);
            }
            #pragma unroll
            for (int p = 0; p < 2; p++) {
                uint32_t q[4];
                ldsm_x4(q, st + bOff + p*(16*RS) + ks*32);
                bh[2*p][0] = q[0]; bh[2*p][1] = q[2];
                bh[2*p+1][0] = q[1]; bh[2*p+1][1] = q[3];
                ldsm_x4(q, st + COMP + bOff + p*(16*RS) + ks*32);
                bl[2*p][0] = q[0]; bl[2*p][1] = q[2];
                bl[2*p+1][0] = q[1]; bl[2*p+1][1] = q[3];
            }
            #pragma unroll
            for (int mt = 0; mt < 4; mt++)
                #pragma unroll
                for (int nt = 0; nt < 4; nt++) {
                    mma16816(acc[mt][nt], ah[mt], bh[nt]);
                    mma16816(acc[mt][nt], al[mt], bh[nt]);
                    mma16816(acc[mt][nt], ah[mt], bl[nt]);
                }
        }
        if (ch + 1 < nch) {
            char* nst = smem + ((ch+1) & 1) * STAGE;
            split_store(nst, va, tid);
            split_store(nst + 2*COMP, vb, tid);
        }
        __syncthreads();
    }

    // ------------- epilogue -------------
    if (flags & 4) {
        // Gram wrapped-diagonal reduction: bin i = (m_local - n_local) + 127
        float* bins = (float*)smem;
        for (int i = tid; i < 255; i += 256) bins[i] = 0.f;
        __syncthreads();
        #pragma unroll
        for (int mt = 0; mt < 4; mt++)
            #pragma unroll
            for (int nt = 0; nt < 4; nt++)
                #pragma unroll
                for (int r = 0; r < 4; r++) {
                    int ml = wm*64 + mt*16 + (lane >> 2) + ((r >> 1) & 1)*8;
                    int nl = wn*32 + nt*8 + (lane & 3)*2 + (r & 1);
                    atomicAdd(&bins[ml - nl + 127], acc[mt][nt][r]);
                }
        __syncthreads();
        for (int i = tid; i < 255; i += 256) {
            int tau = m0 - n0 - 127 + i;
            tau %= LSEQ; if (tau < 0) tau += LSEQ;
            atomicAdd(&MV[bz*LSEQ + tau], bins[i]);
        }
    } else {
        float* Cb = C + bz * sC;
        #pragma unroll
        for (int mt = 0; mt < 4; mt++)
            #pragma unroll
            for (int nt = 0; nt < 4; nt++) {
                int nb = n0 + wn*32 + nt*8 + (lane & 3)*2;
                #pragma unroll
                for (int h = 0; h < 2; h++) {
                    int m = m0 + wm*64 + mt*16 + (lane >> 2) + h*8;
                    float2 v = make_float2(acc[mt][nt][2*h], acc[mt][nt][2*h+1]);
                    if (bias) { v.x += bias[nb]; v.y += bias[nb+1]; }
                    if (flags & 2) {
                        float2 rr = *(const float2*)&resid[(long long)m*N + nb];
                        v.x += rr.x; v.y += rr.y;
                    }
                    if (flags & 1) { v.x = fmaxf(v.x, 0.f); v.y = fmaxf(v.y, 0.f); }
                    *(float2*)&Cb[(long long)m*N + nb] = v;
                }
            }
    }
}

// ------------------------- top-7 delays + per-batch softmax weights -------------------------
__global__ void topk_kernel(const float* __restrict__ MV, int* __restrict__ idx_out,
                            float* __restrict__ w_out)
{
    __shared__ float g[LSEQ];
    __shared__ float rv[256];
    __shared__ int   ri[256];
    __shared__ int   s_idx[TOPK];
    int tid = threadIdx.x;   // 256

    for (int t = tid; t < LSEQ; t += 256) {
        float s = 0.f;
        for (int b = 0; b < BB; b++) s += MV[b*LSEQ + t];
        g[t] = s;
    }
    __syncthreads();

    for (int it = 0; it < TOPK; it++) {
        float best = -INFINITY; int bi = 0;
        for (int t = tid; t < LSEQ; t += 256)
            if (g[t] > best) { best = g[t]; bi = t; }
        rv[tid] = best; ri[tid] = bi;
        __syncthreads();
        for (int s = 128; s > 0; s >>= 1) {
            if (tid < s && rv[tid + s] > rv[tid]) { rv[tid] = rv[tid+s]; ri[tid] = ri[tid+s]; }
            __syncthreads();
        }
        if (tid == 0) { s_idx[it] = ri[0]; g[ri[0]] = -INFINITY; idx_out[it] = ri[0]; }
        __syncthreads();
    }

    if (tid < BB) {
        int b = tid;
        float wv[TOPK]; float mx = -INFINITY;
        for (int i = 0; i < TOPK; i++) {
            wv[i] = MV[b*LSEQ + s_idx[i]] * (1.0f / (float)DIM);
            mx = fmaxf(mx, wv[i]);
        }
        float s = 0.f;
        for (int i = 0; i < TOPK; i++) { wv[i] = expf(wv[i] - mx); s += wv[i]; }
        for (int i = 0; i < TOPK; i++) w_out[b*TOPK + i] = wv[i] / s;
    }
}

// ------------------------- time-delay aggregation -------------------------
__global__ void aggregate_kernel(const float* __restrict__ V, const int* __restrict__ idx,
                                 const float* __restrict__ w, float* __restrict__ O)
{
    int bt = blockIdx.x;
    int b  = bt / LSEQ, t = bt % LSEQ;
    __shared__ int   s_i[TOPK];
    __shared__ float s_w[TOPK];
    if (threadIdx.x < TOPK) { s_i[threadIdx.x] = idx[threadIdx.x]; s_w[threadIdx.x] = w[b*TOPK + threadIdx.x]; }
    __syncthreads();
    int d4 = threadIdx.x;   // 128 threads, float4 over D=512
    float4 acc = {0.f,0.f,0.f,0.f};
    #pragma unroll
    for (int i = 0; i < TOPK; i++) {
        int tt = t + s_i[i]; if (tt >= LSEQ) tt -= LSEQ;
        float4 v = *(const float4*)&V[((long long)(b*LSEQ + tt))*DIM + d4*4];
        acc.x += s_w[i]*v.x; acc.y += s_w[i]*v.y; acc.z += s_w[i]*v.z; acc.w += s_w[i]*v.w;
    }
    *(float4*)&O[((long long)bt)*DIM + d4*4] = acc;
}

// ------------------------- series_decomp: dst = src - movavg_25(src) -------------------------
__global__ void decomp_kernel(const float* __restrict__ src, float* __restrict__ dst)
{
    int d  = blockIdx.x * blockDim.x + threadIdx.x;  // 0..511
    int b  = blockIdx.y;
    int t0 = blockIdx.z * 128;
    const float* s = src + (long long)b * LSEQ * DIM + d;
    float*       o = dst + (long long)b * LSEQ * DIM + d;

    float sum = 0.f;
    for (int j = t0 - 12; j <= t0 + 12; j++) {
        int jc = j; if (jc < 0) jc = 0; if (jc > LSEQ-1) jc = LSEQ-1;
        sum += s[(long long)jc * DIM];
    }
    for (int t = t0; t < t0 + 128; t++) {
        o[(long long)t * DIM] = s[(long long)t * DIM] - sum * (1.0f/25.0f);
        int ja = t + 13; if (ja > LSEQ-1) ja = LSEQ-1;
        int jr = t - 12; if (jr < 0) jr = 0;
        sum += s[(long long)ja * DIM] - s[(long long)jr * DIM];
    }
}

// ------------------------- im2col for circular conv1d k=3 -------------------------
__global__ void im2col_kernel(const float* __restrict__ x, float* __restrict__ ic)
{
    long long i = (long long)blockIdx.x * blockDim.x + threadIdx.x;
    const long long total = (long long)BB * LSEQ * 3 * (DIM/4);
    if (i >= total) return;
    int c4 = (int)(i % (DIM/4));
    long long r = i / (DIM/4);
    int j = (int)(r % 3);
    long long bt = r / 3;
    int t = (int)(bt % LSEQ);
    int b = (int)(bt / LSEQ);
    int ts = t + j - 1; if (ts < 0) ts += LSEQ; if (ts >= LSEQ) ts -= LSEQ;
    float4 v = *(const float4*)&x[((long long)(b*LSEQ + ts))*DIM + c4*4];
    *(float4*)&ic[(bt*3 + j)*DIM + (long long)c4*4] = v;
}

// ------------------------- repack conv weight (O,I,3) -> [O, 3*I] -------------------------
__global__ void repack_kernel(const float* __restrict__ W, float* __restrict__ out)
{
    int i = blockIdx.x * blockDim.x + threadIdx.x;
    const int total = DIM * 3 * DIM;
    if (i >= total) return;
    int o = i / (3*DIM);
    int k = i % (3*DIM);
    int j = k / DIM, c = k % DIM;
    out[i] = W[((long long)o*DIM + c)*3 + j];
}

// ------------------------- host orchestration -------------------------
static void launch_tc(const float* A, const float* Bw, const float* bias, const float* resid,
                      float* C, float* MV, int M, int N, int K, int batch,
                      long long sA, long long sB, long long sC, int flags)
{
    dim3 grid(N/128, M/128, batch);
    gemm_tc_kernel<<<grid, 256, DYN_SMEM>>>(A, Bw, bias, resid, C, MV, M, N, K, sA, sB, sC, flags);
}

extern "C" void kernel_launch(void* const* d_in, const int* in_sizes, int n_in,
                              void* d_out, int out_size)
{
    const float* x_s      = (const float*)d_in[0];
    const float* x_w      = (const float*)d_in[1];
    const float* wc1_W    = (const float*)d_in[2];
    const float* wc1_b    = (const float*)d_in[3];
    const float* wc2_W    = (const float*)d_in[4];
    const float* wc2_b    = (const float*)d_in[5];
    const float* attn_W   = (const float*)d_in[6];
    const float* attn_b   = (const float*)d_in[7];
    const float* wc1_proj = (const float*)d_in[8];
    const float* wc2_proj = (const float*)d_in[9];
    const float* conv1_W  = (const float*)d_in[10];
    const float* conv2_W  = (const float*)d_in[11];

    float* out_res = (float*)d_out;
    float* out_xw  = out_res + (long long)MROWS * DIM;

    cudaFuncSetAttribute(gemm_tc_kernel, cudaFuncAttributeMaxDynamicSharedMemorySize, DYN_SMEM);

    float *pQ,*pK,*pV,*pO,*pT1,*pT2,*pT3,*pT4,*pFF,*pIC,*pWT,*pMV,*pWTS;
    int* pIDX;
    cudaGetSymbolAddress((void**)&pQ,  g_Q);
    cudaGetSymbolAddress((void**)&pK,  g_K);
    cudaGetSymbolAddress((void**)&pV,  g_V);
    cudaGetSymbolAddress((void**)&pO,  g_O);
    cudaGetSymbolAddress((void**)&pT1, g_T1);
    cudaGetSymbolAddress((void**)&pT2, g_T2);
    cudaGetSymbolAddress((void**)&pT3, g_T3);
    cudaGetSymbolAddress((void**)&pT4, g_T4);
    cudaGetSymbolAddress((void**)&pFF, g_FF);
    cudaGetSymbolAddress((void**)&pIC, g_IC);
    cudaGetSymbolAddress((void**)&pWT, g_WT);
    cudaGetSymbolAddress((void**)&pMV, g_MV);
    cudaGetSymbolAddress((void**)&pWTS,g_WTS);
    cudaGetSymbolAddress((void**)&pIDX,g_IDX);

    const long long DD2 = (long long)DIM * DIM;

    auto run_attn = [&](const float* qin, const float* kin, const float* W, const float* bvec,
                        const float* resid, float* dest)
    {
        launch_tc(qin, W + 0*DD2, bvec + 0*DIM, nullptr, pQ, nullptr, MROWS, DIM, DIM, 1, 0,0,0, 0);
        launch_tc(kin, W + 1*DD2, bvec + 1*DIM, nullptr, pK, nullptr, MROWS, DIM, DIM, 1, 0,0,0, 0);
        launch_tc(kin, W + 2*DD2, bvec + 2*DIM, nullptr, pV, nullptr, MROWS, DIM, DIM, 1, 0,0,0, 0);
        cudaMemsetAsync(pMV, 0, BB*LSEQ*sizeof(float));
        // per-batch Gram with fused wrapped-diagonal reduction into MV
        launch_tc(pQ, pK, nullptr, nullptr, nullptr, pMV, LSEQ, LSEQ, DIM, BB,
                  (long long)LSEQ*DIM, (long long)LSEQ*DIM, 0, 4);
        topk_kernel<<<1, 256>>>(pMV, pIDX, pWTS);
        aggregate_kernel<<<MROWS, 128>>>(pV, pIDX, pWTS, pO);
        launch_tc(pO, W + 3*DD2, bvec + 3*DIM, resid, dest, nullptr, MROWS, DIM, DIM, 1, 0,0,0, 2);
    };

    auto run_embed = [&](const float* x, const float* Wproj, float* dest)
    {
        repack_kernel<<<(DIM*3*DIM + 255)/256, 256>>>(Wproj, pWT);
        im2col_kernel<<<(unsigned)(((long long)BB*LSEQ*3*(DIM/4) + 255)/256), 256>>>(x, pIC);
        launch_tc(pIC, pWT, nullptr, nullptr, dest, nullptr, MROWS, DIM, 3*DIM, 1, 0,0,0, 0);
    };

    // 1) x_s1 = x_s + attn(q=x_w, k=v=x_s ; wc1)          -> T1
    run_attn(x_w, x_s, wc1_W, wc1_b, x_s, pT1);
    // 2) x_w1 = token_embed(x_w, wc1_proj)                 -> T2
    run_embed(x_w, wc1_proj, pT2);
    // 3) x_s2 = x_s1 + attn(x_s1 ; attn_W)                 -> T3
    run_attn(pT1, pT1, attn_W, attn_b, pT1, pT3);
    // 4) x_s3 = decomp(x_s2)                               -> T4
    decomp_kernel<<<dim3(DIM/128, BB, LSEQ/128), 128>>>(pT3, pT4);
    // 5) x_s4 = x_s3 + attn(q=x_w1, k=v=x_s3 ; wc2)        -> T1
    run_attn(pT2, pT4, wc2_W, wc2_b, pT4, pT1);
    // 6) x_w_new = token_embed(x_w1, wc2_proj)             -> out_xw
    run_embed(pT2, wc2_proj, out_xw);
    // 7) FFN: y = relu(x_s4 @ conv1^T) @ conv2^T ; tmp = x_s4 + y  -> T3
    launch_tc(pT1, conv1_W, nullptr, nullptr, pFF, nullptr, MROWS, DFF, DIM, 1, 0,0,0, 1);
    launch_tc(pFF, conv2_W, nullptr, pT1, pT3, nullptr, MROWS, DIM, DFF, 1, 0,0,0, 2);
    // 8) res = decomp(tmp)                                 -> out_res
    decomp_kernel<<<dim3(DIM/128, BB, LSEQ/128), 128>>>(pT3, out_res);
}